// round 1
// baseline (speedup 1.0000x reference)
#include <cuda_runtime.h>

#define SEQ   2048
#define BATCH 128
#define INP   64
#define HID   256
#define GH    1024   // 4*HID
#define OUTD  64
#define NBLK  128    // persistent blocks for recurrent kernel

// ---------------- scratch (static device allocations; no cudaMalloc) --------
__device__ float g_xw[(size_t)SEQ * BATCH * GH];   // 1 GiB: x @ W_ih^T + b
__device__ float g_hs[(size_t)SEQ * BATCH * HID];  // 256 MiB: h history
__device__ unsigned g_cnt;
__device__ volatile unsigned g_gen;

// =============================================================
// Kernel A: xw[m][g] = sum_i x[m][i]*W_ih[g][i] + b[g]
// M = SEQ*BATCH = 262144, N = 1024, K = 64.
// Block tile 64(M) x 128(N), 256 threads, thread tile 4x8, float4 K-vec.
// =============================================================
__global__ void __launch_bounds__(256) k_gemm_xw(const float* __restrict__ x,
                                                 const float* __restrict__ Wih,
                                                 const float* __restrict__ bias)
{
    extern __shared__ float4 smA[];
    float4* Xs = smA;            // 64 rows x 19 f4 (16 used + pad)
    float4* Ws = smA + 64 * 19;  // 128 rows x 19 f4

    const int t  = threadIdx.x;
    const int m0 = blockIdx.x * 64;
    const int n0 = blockIdx.y * 128;

    const float4* x4 = (const float4*)x;
    const float4* w4 = (const float4*)Wih;

    #pragma unroll
    for (int idx = t; idx < 64 * 16; idx += 256) {
        int r = idx >> 4, c = idx & 15;
        Xs[r * 19 + c] = x4[(size_t)(m0 + r) * 16 + c];
    }
    #pragma unroll
    for (int idx = t; idx < 128 * 16; idx += 256) {
        int r = idx >> 4, c = idx & 15;
        Ws[r * 19 + c] = w4[(size_t)(n0 + r) * 16 + c];
    }
    __syncthreads();

    const int tx = t & 15, ty = t >> 4;
    float acc[4][8];
    #pragma unroll
    for (int i = 0; i < 4; i++)
        #pragma unroll
        for (int j = 0; j < 8; j++) acc[i][j] = 0.f;

    #pragma unroll
    for (int k4 = 0; k4 < 16; k4++) {
        float4 a[4], bv[8];
        #pragma unroll
        for (int i = 0; i < 4; i++) a[i] = Xs[(ty + 16 * i) * 19 + k4];
        #pragma unroll
        for (int j = 0; j < 8; j++) bv[j] = Ws[(tx + 16 * j) * 19 + k4];
        #pragma unroll
        for (int i = 0; i < 4; i++)
            #pragma unroll
            for (int j = 0; j < 8; j++)
                acc[i][j] += a[i].x * bv[j].x + a[i].y * bv[j].y +
                             a[i].z * bv[j].z + a[i].w * bv[j].w;
    }
    #pragma unroll
    for (int i = 0; i < 4; i++) {
        int m = m0 + ty + 16 * i;
        #pragma unroll
        for (int j = 0; j < 8; j++) {
            int n = n0 + tx + 16 * j;
            g_xw[(size_t)m * GH + n] = acc[i][j] + __ldg(&bias[n]);
        }
    }
}

// =============================================================
// Kernel B: persistent recurrent LSTM scan.
// 128 blocks = 8 batch-groups(16 b) x 16 unit-groups(16 u => 64 gate rows).
// W_hh slice resident in SMEM for all 2048 steps. One grid barrier / step.
// =============================================================
__global__ void __launch_bounds__(256, 1) k_lstm(const float* __restrict__ h0,
                                                 const float* __restrict__ c0,
                                                 const float* __restrict__ Whh)
{
    extern __shared__ float smR[];
    float* Wsm = smR;                 // 64 x 260 (padded)
    float* Hsm = smR + 64 * 260;      // 16 x 256
    float* Lsm = Hsm + 16 * 256;      // 16 x 80 (lin, padded)
    float* Csm = Lsm + 16 * 80;       // 16 x 16

    const int t   = threadIdx.x;
    const int bg  = blockIdx.x >> 4;   // 0..7
    const int ug  = blockIdx.x & 15;   // 0..15
    const int b0g = bg << 4;           // global batch base
    const int u0  = ug << 4;           // global unit base

    // --- load W_hh slice (once): local row r -> global gate row
    #pragma unroll
    for (int idx = t; idx < 64 * 64; idx += 256) {
        int r = idx >> 6, c4 = idx & 63;
        int grow = ((r >> 4) << 8) + u0 + (r & 15);
        float4 v = ((const float4*)Whh)[(size_t)grow * 64 + c4];
        *(float4*)(Wsm + r * 260 + (c4 << 2)) = v;
    }
    // --- init Hsm from h0, Csm from c0
    for (int idx = t; idx < 16 * 64; idx += 256) {
        int b = idx >> 6, c4 = idx & 63;
        ((float4*)(Hsm + (b << 8)))[c4] = ((const float4*)h0)[(size_t)(b0g + b) * 64 + c4];
    }
    {
        int b = t >> 4, jj = t & 15;
        Csm[(b << 4) + jj] = c0[(size_t)(b0g + b) * HID + u0 + jj];
    }
    __syncthreads();

    // lane mapping: warp w: rows 32*(w&1)..+31, batches 4*(w>>1)..+3
    const int w    = t >> 5, lane = t & 31;
    const int lr   = ((w & 1) << 5) + lane;          // local gate row 0..63
    const int bloc = (w >> 1) << 2;                  // local batch base
    const int grow = ((lr >> 4) << 8) + u0 + (lr & 15);

    const float4* Wrow = (const float4*)(Wsm + lr * 260);
    const float4* Hb0  = (const float4*)(Hsm + ((bloc + 0) << 8));
    const float4* Hb1  = (const float4*)(Hsm + ((bloc + 1) << 8));
    const float4* Hb2  = (const float4*)(Hsm + ((bloc + 2) << 8));
    const float4* Hb3  = (const float4*)(Hsm + ((bloc + 3) << 8));

    for (int step = 0; step < SEQ; step++) {
        // prefetch xw for this thread's 4 (batch,row) outputs
        const float* xwp = g_xw + ((size_t)step * BATCH + b0g + bloc) * GH + grow;
        float xv0 = xwp[0];
        float xv1 = xwp[GH];
        float xv2 = xwp[2 * GH];
        float xv3 = xwp[3 * GH];

        float4 a0 = {0.f,0.f,0.f,0.f}, a1 = a0, a2 = a0, a3 = a0;
        #pragma unroll 8
        for (int k4 = 0; k4 < 64; k4++) {
            float4 wv  = Wrow[k4];
            float4 h0v = Hb0[k4];
            a0.x += wv.x * h0v.x; a0.y += wv.y * h0v.y;
            a0.z += wv.z * h0v.z; a0.w += wv.w * h0v.w;
            float4 h1v = Hb1[k4];
            a1.x += wv.x * h1v.x; a1.y += wv.y * h1v.y;
            a1.z += wv.z * h1v.z; a1.w += wv.w * h1v.w;
            float4 h2v = Hb2[k4];
            a2.x += wv.x * h2v.x; a2.y += wv.y * h2v.y;
            a2.z += wv.z * h2v.z; a2.w += wv.w * h2v.w;
            float4 h3v = Hb3[k4];
            a3.x += wv.x * h3v.x; a3.y += wv.y * h3v.y;
            a3.z += wv.z * h3v.z; a3.w += wv.w * h3v.w;
        }
        Lsm[(bloc + 0) * 80 + lr] = (a0.x + a0.y) + (a0.z + a0.w) + xv0;
        Lsm[(bloc + 1) * 80 + lr] = (a1.x + a1.y) + (a1.z + a1.w) + xv1;
        Lsm[(bloc + 2) * 80 + lr] = (a2.x + a2.y) + (a2.z + a2.w) + xv2;
        Lsm[(bloc + 3) * 80 + lr] = (a3.x + a3.y) + (a3.z + a3.w) + xv3;
        __syncthreads();

        // gate update: thread -> (b = t/16, jj = t%16)
        {
            int b = t >> 4, jj = t & 15;
            float iv = Lsm[b * 80 + jj];
            float fv = Lsm[b * 80 + 16 + jj];
            float gv = Lsm[b * 80 + 32 + jj];
            float ov = Lsm[b * 80 + 48 + jj];
            float ig = 1.f / (1.f + __expf(-iv));
            float fg = 1.f / (1.f + __expf(-fv));
            float gg = tanhf(gv);
            float og = 1.f / (1.f + __expf(-ov));
            float cc = fg * Csm[(b << 4) + jj] + ig * gg;
            Csm[(b << 4) + jj] = cc;
            float hh = og * tanhf(cc);
            g_hs[((size_t)step * BATCH + b0g + b) * HID + u0 + jj] = hh;
        }
        __threadfence();
        __syncthreads();

        // --- grid barrier (replay-safe: relative generation) ---
        if (t == 0) {
            unsigned cur = g_gen;
            __threadfence();
            if (atomicAdd(&g_cnt, 1u) == (unsigned)(NBLK - 1)) {
                atomicExch(&g_cnt, 0u);
                __threadfence();
                g_gen = cur + 1u;
            } else {
                while (g_gen == cur) { }
            }
            __threadfence();
        }
        __syncthreads();

        // reload full h for our 16 batches
        if (step < SEQ - 1) {
            const float4* hs4 = (const float4*)(g_hs + (size_t)step * BATCH * HID);
            for (int idx = t; idx < 16 * 64; idx += 256) {
                int b = idx >> 6, c4 = idx & 63;
                ((float4*)(Hsm + (b << 8)))[c4] = hs4[(size_t)(b0g + b) * 64 + c4];
            }
            __syncthreads();
        }
    }
}

// =============================================================
// Kernel C: out[m][o] = sum_h hs[m][h]*W_out[o][h] + b_out[o]
// M = 262144, N = 64, K = 256. Block tile 64x64, thread 4x4, K in 4 chunks.
// =============================================================
__global__ void __launch_bounds__(256) k_gemm_out(const float* __restrict__ Wout,
                                                  const float* __restrict__ bout,
                                                  float* __restrict__ out)
{
    extern __shared__ float4 smC[];
    float4* Hs = smC;            // 64 x 19
    float4* Ws = smC + 64 * 19;  // 64 x 19

    const int t  = threadIdx.x;
    const int m0 = blockIdx.x * 64;
    const int tx = t & 15, ty = t >> 4;

    float acc[4][4];
    #pragma unroll
    for (int i = 0; i < 4; i++)
        #pragma unroll
        for (int j = 0; j < 4; j++) acc[i][j] = 0.f;

    const float4* hs4 = (const float4*)g_hs;
    const float4* wo4 = (const float4*)Wout;

    for (int kc = 0; kc < 4; kc++) {
        __syncthreads();
        #pragma unroll
        for (int idx = t; idx < 64 * 16; idx += 256) {
            int r = idx >> 4, c = idx & 15;
            Hs[r * 19 + c] = hs4[(size_t)(m0 + r) * 64 + kc * 16 + c];
            Ws[r * 19 + c] = wo4[(size_t)r * 64 + kc * 16 + c];
        }
        __syncthreads();
        #pragma unroll
        for (int k4 = 0; k4 < 16; k4++) {
            float4 a[4], bv[4];
            #pragma unroll
            for (int i = 0; i < 4; i++) a[i] = Hs[(ty + 16 * i) * 19 + k4];
            #pragma unroll
            for (int j = 0; j < 4; j++) bv[j] = Ws[(tx + 16 * j) * 19 + k4];
            #pragma unroll
            for (int i = 0; i < 4; i++)
                #pragma unroll
                for (int j = 0; j < 4; j++)
                    acc[i][j] += a[i].x * bv[j].x + a[i].y * bv[j].y +
                                 a[i].z * bv[j].z + a[i].w * bv[j].w;
        }
    }
    #pragma unroll
    for (int i = 0; i < 4; i++) {
        size_t m = (size_t)(m0 + ty + 16 * i);
        #pragma unroll
        for (int j = 0; j < 4; j++) {
            int n = tx + 16 * j;
            out[m * OUTD + n] = acc[i][j] + __ldg(&bout[n]);
        }
    }
}

// =============================================================
extern "C" void kernel_launch(void* const* d_in, const int* in_sizes, int n_in,
                              void* d_out, int out_size)
{
    (void)in_sizes; (void)n_in; (void)out_size;
    const float* x    = (const float*)d_in[0];
    const float* h0   = (const float*)d_in[1];
    const float* c0   = (const float*)d_in[2];
    const float* Wih  = (const float*)d_in[3];
    const float* Whh  = (const float*)d_in[4];
    const float* b    = (const float*)d_in[5];
    const float* Wout = (const float*)d_in[6];
    const float* bout = (const float*)d_in[7];
    float* out = (float*)d_out;

    const int smA = (64 + 128) * 19 * 16;                       // 58368 B
    const int smR = (64 * 260 + 16 * 256 + 16 * 80 + 16 * 16) * 4;  // 89088 B
    const int smC = (64 + 64) * 19 * 16;                        // 38912 B

    static int attr_done = -1;
    // (setting attributes is idempotent; call every time, it is not a stream op)
    cudaFuncSetAttribute(k_gemm_xw, cudaFuncAttributeMaxDynamicSharedMemorySize, smA);
    cudaFuncSetAttribute(k_lstm,    cudaFuncAttributeMaxDynamicSharedMemorySize, smR);
    cudaFuncSetAttribute(k_gemm_out, cudaFuncAttributeMaxDynamicSharedMemorySize, smC);
    (void)attr_done;

    dim3 gridA((SEQ * BATCH) / 64, GH / 128);
    k_gemm_xw<<<gridA, 256, smA>>>(x, Wih, b);

    k_lstm<<<NBLK, 256, smR>>>(h0, c0, Whh);

    k_gemm_out<<<(SEQ * BATCH) / 64, 256, smC>>>(Wout, bout, out);
}